// round 14
// baseline (speedup 1.0000x reference)
#include <cuda_runtime.h>

#define S 64
#define D 524288            // 512*32*32
#define DQ (D / 4)          // 131072 float4 columns per row

// ---- strip tiling: 128 float4 columns x 32-row strip, 2048 blocks ----
#define TB_THREADS 128
#define CCHUNKS (DQ / TB_THREADS)   // 1024 column chunks
#define HSTRIPS 2                   // two 32-row strips
#define NBLOCKS (CCHUNKS * HSTRIPS) // 2048

// scratch (no device allocations allowed)
// g_part[bid*64 + g*16 + k]: block bid, row-group g (8 rows), k<8 -> N, k>=8 -> A
__device__ float g_part[NBLOCKS * 64];
__device__ float g_coeff[3 * S];            // [cp(64)][cc(64)][cn(64)]

__device__ __forceinline__ float dot4(float4 a, float4 b) {
    return a.x * b.x + a.y * b.y + a.z * b.z + a.w * b.w;
}

// Pass 1: block = (col chunk cx, strip h). Each thread owns one float4 column
// and rolls over 32 rows in four 8-row groups, carrying the halo row in a
// register: 33 row-loads per 32 rows (vs 36 before -> 132MB total reads).
// Each group's 8 loads are front-batched (MLP=8); the 16 partials are reduced
// by the conflict-free smem transpose.
__global__ __launch_bounds__(TB_THREADS) void dots_kernel(const float4* __restrict__ q4) {
    const int bid  = blockIdx.y * CCHUNKS + blockIdx.x;
    const int base = blockIdx.y * 32;
    const int col  = blockIdx.x * TB_THREADS + threadIdx.x;

    const int kk  = threadIdx.x & 15;
    const int seg = threadIdx.x >> 4;      // 0..7
    const int w   = threadIdx.x >> 5;      // 0..3

    __shared__ float sh[16][TB_THREADS + 1];
    __shared__ float sh2[16][4];

    // initial window: rows base .. base+8 (no clamp needed: max 40)
    float4 r[9];
#pragma unroll
    for (int k = 0; k < 9; k++)
        r[k] = q4[(size_t)(base + k) * DQ + col];

#pragma unroll
    for (int g = 0; g < 4; g++) {
        float v[16];
#pragma unroll
        for (int k = 0; k < 8; k++) {
            v[k]     = dot4(r[k], r[k]);        // N[base+8g+k]
            v[k + 8] = dot4(r[k], r[k + 1]);    // A[base+8g+k]
        }

        // issue next group's loads early (overlap with the reduction)
        if (g < 3) {
            r[0] = r[8];
#pragma unroll
            for (int k = 1; k < 9; k++) {
                int row = base + g * 8 + 8 + k;
                if (row > S - 1) row = S - 1;   // only strip h=1, g->3 halo; A[63] never read
                r[k] = q4[(size_t)row * DQ + col];
            }
        }

#pragma unroll
        for (int k = 0; k < 16; k++) sh[k][threadIdx.x] = v[k];
        __syncthreads();

        float acc = 0.f;
#pragma unroll
        for (int j = 0; j < 16; j++) acc += sh[kk][seg * 16 + j];
        acc += __shfl_xor_sync(0xFFFFFFFFu, acc, 16);   // combine adjacent segs

        if ((threadIdx.x & 16) == 0)
            sh2[kk][w] = acc;
        __syncthreads();

        if (threadIdx.x < 16) {
            const float sum = sh2[threadIdx.x][0] + sh2[threadIdx.x][1]
                            + sh2[threadIdx.x][2] + sh2[threadIdx.x][3];
            g_part[bid * 64 + g * 16 + threadIdx.x] = sum;   // 64B coalesced
        }
    }
}

// Pass 2 (tiny): reduce the 2048 per-block partial sets (coalesced float2
// reads), then entropy branch ladder + softmax-of-2 -> (cp, cc, cn).
__global__ void coeff_kernel(const float* __restrict__ ent) {
    const int w    = threadIdx.x >> 5;   // 8 warps
    const int lane = threadIdx.x & 31;

    const float2* gp = (const float2*)g_part;   // gp[bid*32 + j], j<32
    float2 acc0 = {0.f, 0.f}, acc1 = {0.f, 0.f};
    for (int i = 0; i < 128; i++) {             // bids w+8i < 1024  -> strip h=0
        const float2 t = gp[(w + 8 * i) * 32 + lane];
        acc0.x += t.x; acc0.y += t.y;
    }
    for (int i = 128; i < 256; i++) {           // bids >= 1024     -> strip h=1
        const float2 t = gp[(w + 8 * i) * 32 + lane];
        acc1.x += t.x; acc1.y += t.y;
    }

    __shared__ float smA[8][2][64];
    smA[w][0][2 * lane]     = acc0.x;
    smA[w][0][2 * lane + 1] = acc0.y;
    smA[w][1][2 * lane]     = acc1.x;
    smA[w][1][2 * lane + 1] = acc1.y;
    __syncthreads();

    __shared__ float shN[S], shA[S];
    if (threadIdx.x < 128) {
        const int h  = threadIdx.x >> 6;
        const int pl = threadIdx.x & 63;
        float sum = 0.f;
#pragma unroll
        for (int j = 0; j < 8; j++) sum += smA[j][h][pl];
        const int g  = pl >> 4;
        const int k2 = pl & 15;
        const int srow = h * 32 + g * 8 + (k2 & 7);
        if (k2 < 8) shN[srow] = sum; else shA[srow] = sum;
    }
    __syncthreads();

    const int s = threadIdx.x;
    if (s >= S) return;

    int k1, k2;
    if (s == 0) {
        const int b0 = (ent[0] >= ent[1]) ? 1 : 0;
        k1 = b0; k2 = b0;
    } else if (s == S - 1) {
        const int bL = (ent[S - 1] >= ent[S - 2]) ? (S - 2) : (S - 1);
        k1 = bL; k2 = bL;
    } else {
        const float e  = ent[s];
        const float ep = ent[s - 1];
        const float en = ent[s + 1];
        const bool ge_next = e >= en, ge_prev = e >= ep;
        const bool le_next = e <= en, le_prev = e <= ep;
        if (ge_next && ge_prev)      { k1 = s - 1; k2 = s + 1; }
        else if (le_next && ge_prev) { k1 = s - 1; k2 = s;     }
        else if (ge_next && le_prev) { k1 = s;     k2 = s + 1; }
        else                         { k1 = s;     k2 = s;     }
    }

    const float d1 = (k1 == s) ? shN[s] : ((k1 == s - 1) ? shA[s - 1] : shA[s]);
    const float d2 = (k2 == s) ? shN[s] : ((k2 == s - 1) ? shA[s - 1] : shA[s]);

    const float scale = rsqrtf((float)D);
    const float s1 = d1 * scale, s2 = d2 * scale;
    const float m  = fmaxf(s1, s2);
    float w1 = expf(s1 - m), w2 = expf(s2 - m);
    const float inv = 1.f / (w1 + w2);
    w1 *= inv; w2 *= inv;

    float cp = 0.f, cc = 0.f, cn = 0.f;
    if (k1 == s - 1) cp += w1; else if (k1 == s) cc += w1; else cn += w1;
    if (k2 == s - 1) cp += w2; else if (k2 == s) cc += w2; else cn += w2;

    g_coeff[s]       = cp;
    g_coeff[64 + s]  = cc;
    g_coeff[128 + s] = cn;
}

// Pass 3: out[s] = cp[s]*q[s-1] + cc[s]*q[s] + cn[s]*q[s+1].
// Same strip decomposition: each thread rolls a 3-row window across its
// 32-row strip carrying 2 rows between 8-row groups: 34 row-loads per 32
// output rows (136MB reads vs 160MB before). 8 loads front-batched per
// group. Streaming stores for the output. Blocks walk in reverse order
// (cheap; harvests whatever L2 tail survives).
__global__ __launch_bounds__(TB_THREADS) void out_kernel(const float4* __restrict__ q4,
                                                         float4* __restrict__ o4) {
    const int lin  = blockIdx.x + CCHUNKS * blockIdx.y;
    const int rlin = (NBLOCKS - 1) - lin;
    const int cx   = rlin & (CCHUNKS - 1);
    const int h    = rlin >> 10;
    const int base = h * 32;
    const int col  = cx * TB_THREADS + threadIdx.x;

    __shared__ float scp[32], scc[32], scn[32];
    if (threadIdx.x < 32) {
        scp[threadIdx.x] = g_coeff[base + threadIdx.x];
        scc[threadIdx.x] = g_coeff[64 + base + threadIdx.x];
        scn[threadIdx.x] = g_coeff[128 + base + threadIdx.x];
    }
    __syncthreads();

    const int rprev = (base > 0) ? (base - 1) : 0;   // cp[0]==0 covers clamp
    float4 a = q4[(size_t)rprev * DQ + col];
    float4 b = q4[(size_t)base * DQ + col];

#pragma unroll
    for (int g = 0; g < 4; g++) {
        float4 n[8];
#pragma unroll
        for (int k = 0; k < 8; k++) {
            int row = base + g * 8 + 1 + k;
            if (row > S - 1) row = S - 1;            // cn[63]==0 covers clamp
            n[k] = q4[(size_t)row * DQ + col];
        }

        const int sl = g * 8;
#pragma unroll
        for (int i = 0; i < 8; i++) {
            const float cp = scp[sl + i], cc = scc[sl + i], cn = scn[sl + i];
            const float4 ra = (i == 0) ? a : ((i == 1) ? b : n[i - 2]);
            const float4 rb = (i == 0) ? b : n[i - 1];
            const float4 rc = n[i];
            float4 o;
            o.x = cp * ra.x + cc * rb.x + cn * rc.x;
            o.y = cp * ra.y + cc * rb.y + cn * rc.y;
            o.z = cp * ra.z + cc * rb.z + cn * rc.z;
            o.w = cp * ra.w + cc * rb.w + cn * rc.w;
            __stcs(&o4[(size_t)(base + sl + i) * DQ + col], o);
        }
        a = n[6];
        b = n[7];
    }
}

extern "C" void kernel_launch(void* const* d_in, const int* in_sizes, int n_in,
                              void* d_out, int out_size) {
    const float4* q4  = (const float4*)d_in[0];
    const float*  ent = (const float*)d_in[1];
    float4*       o4  = (float4*)d_out;

    dots_kernel<<<dim3(CCHUNKS, HSTRIPS), TB_THREADS>>>(q4);
    coeff_kernel<<<1, 256>>>(ent);
    out_kernel<<<dim3(CCHUNKS, HSTRIPS), TB_THREADS>>>(q4, o4);
}

// round 15
// speedup vs baseline: 1.2443x; 1.2443x over previous
#include <cuda_runtime.h>

#define S 64
#define D 524288            // 512*32*32
#define DQ (D / 4)          // 131072 float4 columns per row

// ---- shared tiling: 256 float4 columns x 8-row group ----
#define TB_THREADS 256
#define CCHUNKS (DQ / TB_THREADS)   // 512
#define SGROUPS 8
#define NTILES (CCHUNKS * SGROUPS)  // 4096

// scratch (no device allocations allowed)
// g_part[p * 512 + cx]; p = k*8+sg, k<8 -> N[sg*8+k], k>=8 -> A[sg*8+k-8]
__device__ float g_part[128 * CCHUNKS];
__device__ float g_sums[128];               // stage-1 reduced targets
__device__ float g_coeff[3 * S];            // [cp(64)][cc(64)][cn(64)]

__device__ __forceinline__ float dot4(float4 a, float4 b) {
    return a.x * b.x + a.y * b.y + a.z * b.z + a.w * b.w;
}

// Pass 1: block = (col chunk cx, s-group sg). One float4 column per thread,
// 9 rows front-batched (MLP=9). 16 partials reduced via conflict-free smem
// transpose (16 STS + 16 LDS + 1 SHFL per thread). (R13 config, proven.)
__global__ __launch_bounds__(TB_THREADS) void dots_kernel(const float4* __restrict__ q4) {
    const int sg  = blockIdx.y;
    const int s0  = sg * 8;
    const int col = blockIdx.x * TB_THREADS + threadIdx.x;

    float4 r[9];
#pragma unroll
    for (int k = 0; k < 9; k++) {
        int row = s0 + k;
        if (row > S - 1) row = S - 1;   // sg==7 halo; its A[63] is never read
        r[k] = q4[(size_t)row * DQ + col];
    }

    float v[16];
#pragma unroll
    for (int k = 0; k < 8; k++) {
        v[k]     = dot4(r[k], r[k]);        // N[s0+k]
        v[k + 8] = dot4(r[k], r[k + 1]);    // A[s0+k]
    }

    __shared__ float sh[16][TB_THREADS + 1];
#pragma unroll
    for (int k = 0; k < 16; k++) sh[k][threadIdx.x] = v[k];
    __syncthreads();

    const int k   = threadIdx.x & 15;
    const int seg = threadIdx.x >> 4;
    float acc = 0.f;
#pragma unroll
    for (int j = 0; j < 16; j++) acc += sh[k][seg * 16 + j];
    acc += __shfl_xor_sync(0xFFFFFFFFu, acc, 16);

    __shared__ float sh2[16][9];
    const int w = threadIdx.x >> 5;
    if ((threadIdx.x & 16) == 0)
        sh2[k][w] = acc;
    __syncthreads();

    if (threadIdx.x < 16) {
        float sum = 0.f;
#pragma unroll
        for (int j = 0; j < 8; j++) sum += sh2[threadIdx.x][j];
        g_part[(threadIdx.x * 8 + sg) * CCHUNKS + blockIdx.x] = sum;
    }
}

// Pass 2a: parallel reduction of the 128 targets. Block p reduces its 512
// partials (2KB, coalesced) -> g_sums[p]. 128 blocks spread over 128 SMs
// instead of one block pulling 256KB alone.
__global__ __launch_bounds__(128) void coeff_stage1(void) {
    const float* src = g_part + (size_t)blockIdx.x * CCHUNKS;
    float acc = 0.f;
#pragma unroll
    for (int m = 0; m < CCHUNKS / 128; m++)     // 4 coalesced loads
        acc += src[threadIdx.x + 128 * m];

#pragma unroll
    for (int off = 16; off > 0; off >>= 1)
        acc += __shfl_xor_sync(0xFFFFFFFFu, acc, off);

    __shared__ float sw[4];
    const int w    = threadIdx.x >> 5;
    const int lane = threadIdx.x & 31;
    if (lane == 0) sw[w] = acc;
    __syncthreads();
    if (threadIdx.x == 0)
        g_sums[blockIdx.x] = sw[0] + sw[1] + sw[2] + sw[3];
}

// Pass 2b (tiny): entropy branch ladder + softmax-of-2 -> (cp, cc, cn).
__global__ void coeff_stage2(const float* __restrict__ ent) {
    const int s = threadIdx.x;
    __shared__ float shN[S], shA[S];
    if (s < S) {
        const int pN = (s & 7) * 8 + (s >> 3);
        shN[s] = g_sums[pN];
        shA[s] = g_sums[pN + 64];
    }
    __syncthreads();
    if (s >= S) return;

    int k1, k2;
    if (s == 0) {
        const int b0 = (ent[0] >= ent[1]) ? 1 : 0;
        k1 = b0; k2 = b0;
    } else if (s == S - 1) {
        const int bL = (ent[S - 1] >= ent[S - 2]) ? (S - 2) : (S - 1);
        k1 = bL; k2 = bL;
    } else {
        const float e  = ent[s];
        const float ep = ent[s - 1];
        const float en = ent[s + 1];
        const bool ge_next = e >= en, ge_prev = e >= ep;
        const bool le_next = e <= en, le_prev = e <= ep;
        if (ge_next && ge_prev)      { k1 = s - 1; k2 = s + 1; }
        else if (le_next && ge_prev) { k1 = s - 1; k2 = s;     }
        else if (ge_next && le_prev) { k1 = s;     k2 = s + 1; }
        else                         { k1 = s;     k2 = s;     }
    }

    const float d1 = (k1 == s) ? shN[s] : ((k1 == s - 1) ? shA[s - 1] : shA[s]);
    const float d2 = (k2 == s) ? shN[s] : ((k2 == s - 1) ? shA[s - 1] : shA[s]);

    const float scale = rsqrtf((float)D);
    const float s1 = d1 * scale, s2 = d2 * scale;
    const float m  = fmaxf(s1, s2);
    float w1 = expf(s1 - m), w2 = expf(s2 - m);
    const float inv = 1.f / (w1 + w2);
    w1 *= inv; w2 *= inv;

    float cp = 0.f, cc = 0.f, cn = 0.f;
    if (k1 == s - 1) cp += w1; else if (k1 == s) cc += w1; else cn += w1;
    if (k2 == s - 1) cp += w2; else if (k2 == s) cc += w2; else cn += w2;

    g_coeff[s]       = cp;
    g_coeff[64 + s]  = cc;
    g_coeff[128 + s] = cn;
}

// Pass 3: out[s] = cp[s]*q[s-1] + cc[s]*q[s] + cn[s]*q[s+1].
// Same 8-row tile as dots but with a rolling 6-row window in TWO 4-row
// halves (reuse 2 rows between halves): ~24 live data regs instead of 40
// -> higher occupancy. Halo re-reads hit L2 (adjacent sg blocks run close
// in time). Streaming stores for the output.
__global__ __launch_bounds__(TB_THREADS) void out_kernel(const float4* __restrict__ q4,
                                                         float4* __restrict__ o4) {
    const int sg  = blockIdx.y;
    const int s0  = sg * 8;
    const int col = blockIdx.x * TB_THREADS + threadIdx.x;

    __shared__ float scp[8], scc[8], scn[8];
    if (threadIdx.x < 8) {
        scp[threadIdx.x] = g_coeff[s0 + threadIdx.x];
        scc[threadIdx.x] = g_coeff[64 + s0 + threadIdx.x];
        scn[threadIdx.x] = g_coeff[128 + s0 + threadIdx.x];
    }
    __syncthreads();

    // half 1: rows s0-1 .. s0+4 (6 loads, front-batched)
    float4 r[6];
#pragma unroll
    for (int k = 0; k < 6; k++) {
        int row = s0 - 1 + k;
        if (row < 0) row = 0;                  // cp[0]==0 covers clamp
        r[k] = q4[(size_t)row * DQ + col];
    }

#pragma unroll
    for (int i = 0; i < 4; i++) {
        const float cp = scp[i], cc = scc[i], cn = scn[i];
        float4 o;
        o.x = cp * r[i].x + cc * r[i + 1].x + cn * r[i + 2].x;
        o.y = cp * r[i].y + cc * r[i + 1].y + cn * r[i + 2].y;
        o.z = cp * r[i].z + cc * r[i + 1].z + cn * r[i + 2].z;
        o.w = cp * r[i].w + cc * r[i + 1].w + cn * r[i + 2].w;
        __stcs(&o4[(size_t)(s0 + i) * DQ + col], o);
    }

    // half 2: rows s0+3 .. s0+8; keep r[4](s0+3), r[5](s0+4), load 4 more
    r[0] = r[4];
    r[1] = r[5];
#pragma unroll
    for (int k = 2; k < 6; k++) {
        int row = s0 + 3 + k;
        if (row > S - 1) row = S - 1;          // cn[63]==0 covers clamp
        r[k] = q4[(size_t)row * DQ + col];
    }

#pragma unroll
    for (int i = 0; i < 4; i++) {
        const float cp = scp[4 + i], cc = scc[4 + i], cn = scn[4 + i];
        float4 o;
        o.x = cp * r[i].x + cc * r[i + 1].x + cn * r[i + 2].x;
        o.y = cp * r[i].y + cc * r[i + 1].y + cn * r[i + 2].y;
        o.z = cp * r[i].z + cc * r[i + 1].z + cn * r[i + 2].z;
        o.w = cp * r[i].w + cc * r[i + 1].w + cn * r[i + 2].w;
        __stcs(&o4[(size_t)(s0 + 4 + i) * DQ + col], o);
    }
}

extern "C" void kernel_launch(void* const* d_in, const int* in_sizes, int n_in,
                              void* d_out, int out_size) {
    const float4* q4  = (const float4*)d_in[0];
    const float*  ent = (const float*)d_in[1];
    float4*       o4  = (float4*)d_out;

    dots_kernel<<<dim3(CCHUNKS, SGROUPS), TB_THREADS>>>(q4);
    coeff_stage1<<<128, 128>>>();
    coeff_stage2<<<1, 64>>>(ent);
    out_kernel<<<dim3(CCHUNKS, SGROUPS), TB_THREADS>>>(q4, o4);
}